// round 1
// baseline (speedup 1.0000x reference)
#include <cuda_runtime.h>
#include <cstdint>

// Problem constants
#define NN   4096
#define INF  256
#define Hh   4
#define Dd   64
#define HD   256         // Hh*Dd
#define TI   64          // i-rows per CTA in aggregation
#define JC   32          // j-chunk
#define JSPLIT 2
#define JPER (NN/JSPLIT) // 2048
#define NCHUNK (JPER/JC) // 64

using u64 = unsigned long long;

// ---------------- device scratch (no runtime allocation allowed) -------------
__device__ float g_h[NN*HD];             // 4 MB : h = x@W
__device__ float g_si[NN*Hh];
__device__ float g_sj[NN*Hh];
__device__ float g_eip[NN*Hh];           // exp(si)
__device__ float g_ein[NN*Hh];           // exp(0.2*si)
__device__ float g_ejp[NN*Hh];           // exp(sj)
__device__ float g_ejn[NN*Hh];           // exp(0.2*sj)
__device__ float g_part[JSPLIT*NN*HD];   // 8 MB partial accumulators
__device__ float g_Z[JSPLIT*NN*Hh];      // partial normalizers

// ---------------- f32x2 packed helpers ---------------------------------------
__device__ __forceinline__ u64 pack2(float x, float y) {
    u64 r; asm("mov.b64 %0, {%1,%2};" : "=l"(r) : "f"(x), "f"(y)); return r;
}
__device__ __forceinline__ float2 unpack2(u64 v) {
    float2 r; asm("mov.b64 {%0,%1}, %2;" : "=f"(r.x), "=f"(r.y) : "l"(v)); return r;
}
__device__ __forceinline__ u64 fma2(u64 a, u64 b, u64 c) {
    u64 d; asm("fma.rn.f32x2 %0, %1, %2, %3;" : "=l"(d) : "l"(a), "l"(b), "l"(c));
    return d;
}

// ---------------- kernel 1: h = x @ W  (64x64 tiles, f32x2) ------------------
__global__ void __launch_bounds__(256) gemm_xw(const float* __restrict__ x,
                                               const float* __restrict__ W) {
    __shared__ float As[16*64];   // [k][m]
    __shared__ float Bs[16*64];   // [k][n]
    const int t = threadIdx.x;
    const int row0 = blockIdx.y * 64;
    const int col0 = blockIdx.x * 64;
    const int tx = t & 15;        // n-tile
    const int ty = t >> 4;        // m-tile (0..15)

    u64 acc[2][4];
    #pragma unroll
    for (int m = 0; m < 2; m++)
        #pragma unroll
        for (int n = 0; n < 4; n++) acc[m][n] = 0ull;

    for (int kb = 0; kb < INF; kb += 16) {
        // A: thread loads 4 k-values for one row, stores transposed [k][m]
        {
            const int aRow = t >> 2;
            const int aK4  = (t & 3) * 4;
            float4 av = *(const float4*)(x + (size_t)(row0 + aRow) * INF + kb + aK4);
            As[(aK4 + 0) * 64 + aRow] = av.x;
            As[(aK4 + 1) * 64 + aRow] = av.y;
            As[(aK4 + 2) * 64 + aRow] = av.z;
            As[(aK4 + 3) * 64 + aRow] = av.w;
        }
        // B: [k][n]
        {
            const int bK  = t >> 4;
            const int bN4 = (t & 15) * 4;
            *(float4*)&Bs[bK * 64 + bN4] =
                *(const float4*)(W + (size_t)(kb + bK) * HD + col0 + bN4);
        }
        __syncthreads();
        #pragma unroll
        for (int k = 0; k < 16; k++) {
            float4 a4 = *(const float4*)&As[k * 64 + ty * 4];
            float4 b4 = *(const float4*)&Bs[k * 64 + tx * 4];
            u64 a01 = pack2(a4.x, a4.y);
            u64 a23 = pack2(a4.z, a4.w);
            u64 bb0 = pack2(b4.x, b4.x), bb1 = pack2(b4.y, b4.y);
            u64 bb2 = pack2(b4.z, b4.z), bb3 = pack2(b4.w, b4.w);
            acc[0][0] = fma2(a01, bb0, acc[0][0]); acc[1][0] = fma2(a23, bb0, acc[1][0]);
            acc[0][1] = fma2(a01, bb1, acc[0][1]); acc[1][1] = fma2(a23, bb1, acc[1][1]);
            acc[0][2] = fma2(a01, bb2, acc[0][2]); acc[1][2] = fma2(a23, bb2, acc[1][2]);
            acc[0][3] = fma2(a01, bb3, acc[0][3]); acc[1][3] = fma2(a23, bb3, acc[1][3]);
        }
        __syncthreads();
    }
    // writeback: rows row0+ty*4+{0..3}, cols col0+tx*4+{0..3}
    #pragma unroll
    for (int mp = 0; mp < 2; mp++) {
        #pragma unroll
        for (int n = 0; n < 4; n++) {
            float2 v = unpack2(acc[mp][n]);
            int r0 = row0 + ty * 4 + mp * 2;
            g_h[(size_t)(r0 + 0) * HD + col0 + tx * 4 + n] = v.x;
            g_h[(size_t)(r0 + 1) * HD + col0 + tx * 4 + n] = v.y;
        }
    }
}

// ---------------- kernel 2: per (node, head) scores + exp tables -------------
__global__ void __launch_bounds__(256) scores_k(const float* __restrict__ a1,
                                                const float* __restrict__ a2) {
    __shared__ float s1[Dd], s2[Dd];
    if (threadIdx.x < Dd)            s1[threadIdx.x]      = a1[threadIdx.x];
    else if (threadIdx.x < 2 * Dd)   s2[threadIdx.x - Dd] = a2[threadIdx.x - Dd];
    __syncthreads();

    const int g  = blockIdx.x * 256 + threadIdx.x;   // 0..N*H-1
    const int n  = g >> 2;
    const int hh = g & 3;
    const float* hrow = g_h + (size_t)n * HD + hh * Dd;
    float si = 0.f, sj = 0.f;
    #pragma unroll
    for (int q = 0; q < 16; q++) {
        float4 hv = ((const float4*)hrow)[q];
        si = fmaf(hv.x, s1[4*q+0], si); sj = fmaf(hv.x, s2[4*q+0], sj);
        si = fmaf(hv.y, s1[4*q+1], si); sj = fmaf(hv.y, s2[4*q+1], sj);
        si = fmaf(hv.z, s1[4*q+2], si); sj = fmaf(hv.z, s2[4*q+2], sj);
        si = fmaf(hv.w, s1[4*q+3], si); sj = fmaf(hv.w, s2[4*q+3], sj);
    }
    g_si[g]  = si;                 g_sj[g]  = sj;
    g_eip[g] = __expf(si);         g_ejp[g] = __expf(sj);
    g_ein[g] = __expf(0.2f * si);  g_ejn[g] = __expf(0.2f * sj);
}

// ---------------- kernel 3: fused masked-softmax aggregation -----------------
// grid (64 i-tiles, 2 j-splits), 256 threads.
// smem: hS [JC][H][2][36] padded halves (9216 f) | wS [JC][TI][H] (8192 f)
//       | sjS/ejpS/ejnS [JC][H] (3*128 f)
#define HS_F4_PER_J   72   // H * (2*36) / 4
#define SMEM_FLOATS  (JC*288 + JC*TI*Hh + 3*JC*Hh)
#define SMEM_BYTES   (SMEM_FLOATS * 4)

__global__ void __launch_bounds__(256) gat_agg(const int* __restrict__ adj) {
    extern __shared__ float sm[];
    float* hS   = sm;                       // JC*288 floats
    float* wS   = sm + JC * 288;            // JC*TI*H
    float* sjS  = wS + JC * TI * Hh;        // JC*H
    float* ejpS = sjS + JC * Hh;
    float* ejnS = ejpS + JC * Hh;

    const int t     = threadIdx.x;
    const int i0    = blockIdx.x * TI;
    const int split = blockIdx.y;
    const int jbase0 = split * JPER;

    // Phase-B thread ids: 2 i's x 1 head x 32 d's per thread
    const int head  = t & 3;
    const int dhalf = (t >> 2) & 1;
    const int ipair = t >> 3;               // 0..31
    const int iB0 = 2 * ipair, iB1 = iB0 + 1;

    // Phase-A thread ids: one i-row, 8 consecutive j's
    const int iA = t >> 2;                  // 0..63
    const int jg = t & 3;

    // hoisted per-i score/exp values (float4 over heads)
    const float4 rsi  = ((const float4*)g_si )[i0 + iA];
    const float4 reip = ((const float4*)g_eip)[i0 + iA];
    const float4 rein = ((const float4*)g_ein)[i0 + iA];

    u64 acc0[16], acc1[16];
    #pragma unroll
    for (int q = 0; q < 16; q++) { acc0[q] = 0ull; acc1[q] = 0ull; }
    float Z0 = 0.f, Z1 = 0.f;

    for (int c = 0; c < NCHUNK; c++) {
        const int jb = jbase0 + c * JC;
        __syncthreads();   // previous Phase B done before smem overwrite

        // stage sj / exp tables for this chunk ([JC][H] contiguous)
        if (t < JC * Hh) {
            int gix = jb * Hh + t;
            sjS[t]  = g_sj[gix];
            ejpS[t] = g_ejp[gix];
            ejnS[t] = g_ejn[gix];
        }
        // stage h tile with padded-half layout: [j][h][dhalf*36 + d%32]
        {
            const float4* src = (const float4*)(g_h + (size_t)jb * HD);
            #pragma unroll
            for (int r = 0; r < 8; r++) {
                int v = r * 256 + t;            // float4 index within chunk
                float4 val = src[v];
                int j = v >> 6, rem = v & 63;
                int hh2 = rem >> 4, q = rem & 15;
                int dh = q >> 3, qq = q & 7;
                ((float4*)hS)[j * HS_F4_PER_J + hh2 * 18 + dh * 9 + qq] = val;
            }
        }
        __syncthreads();

        // Phase A: build weight tile wS[j][i][h]
        {
            const int* arow = adj + (size_t)(i0 + iA) * NN + jb + jg * 8;
            int4 av0 = *(const int4*)arow;
            int4 av1 = *(const int4*)(arow + 4);
            int avv[8] = {av0.x, av0.y, av0.z, av0.w, av1.x, av1.y, av1.z, av1.w};
            #pragma unroll
            for (int jj = 0; jj < 8; jj++) {
                int j = jg * 8 + jj;
                bool edge = avv[jj] > 0;
                float4 sj4  = ((const float4*)sjS )[j];
                float4 ejp4 = ((const float4*)ejpS)[j];
                float4 ejn4 = ((const float4*)ejnS)[j];
                float4 wv;
                wv.x = edge ? ((rsi.x + sj4.x >= 0.f) ? reip.x*ejp4.x : rein.x*ejn4.x) : 0.f;
                wv.y = edge ? ((rsi.y + sj4.y >= 0.f) ? reip.y*ejp4.y : rein.y*ejn4.y) : 0.f;
                wv.z = edge ? ((rsi.z + sj4.z >= 0.f) ? reip.z*ejp4.z : rein.z*ejn4.z) : 0.f;
                wv.w = edge ? ((rsi.w + sj4.w >= 0.f) ? reip.w*ejp4.w : rein.w*ejn4.w) : 0.f;
                ((float4*)wS)[j * TI + iA] = wv;   // [j][i][h] as one float4
            }
        }
        __syncthreads();

        // Phase B: FMA-bound accumulation (f32x2 packed)
        #pragma unroll 4
        for (int j = 0; j < JC; j++) {
            float w0 = wS[j * (TI*Hh) + iB0 * 4 + head];
            float w1 = wS[j * (TI*Hh) + iB1 * 4 + head];
            Z0 += w0; Z1 += w1;
            u64 W0 = pack2(w0, w0);
            u64 W1 = pack2(w1, w1);
            const float4* hp = ((const float4*)hS) + j * HS_F4_PER_J + head * 18 + dhalf * 9;
            #pragma unroll
            for (int q = 0; q < 8; q++) {
                float4 hv = hp[q];
                u64 lo = pack2(hv.x, hv.y);
                u64 hi = pack2(hv.z, hv.w);
                acc0[2*q]   = fma2(lo, W0, acc0[2*q]);
                acc0[2*q+1] = fma2(hi, W0, acc0[2*q+1]);
                acc1[2*q]   = fma2(lo, W1, acc1[2*q]);
                acc1[2*q+1] = fma2(hi, W1, acc1[2*q+1]);
            }
        }
    }

    // writeback partials
    {
        float* base = g_part + (size_t)split * NN * HD;
        float2* p0 = (float2*)(base + (size_t)(i0 + iB0) * HD + head * Dd + dhalf * 32);
        float2* p1 = (float2*)(base + (size_t)(i0 + iB1) * HD + head * Dd + dhalf * 32);
        #pragma unroll
        for (int q = 0; q < 16; q++) { p0[q] = unpack2(acc0[q]); p1[q] = unpack2(acc1[q]); }
        if (dhalf == 0) {
            g_Z[(size_t)split * NN * Hh + (i0 + iB0) * Hh + head] = Z0;
            g_Z[(size_t)split * NN * Hh + (i0 + iB1) * Hh + head] = Z1;
        }
    }
}

// ---------------- kernel 4: combine splits + normalize -----------------------
__global__ void __launch_bounds__(256) epilogue_k(float* __restrict__ out) {
    int e = blockIdx.x * 256 + threadIdx.x;      // 0..N*HD-1
    float p = g_part[e] + g_part[(size_t)NN * HD + e];
    int i = e >> 8;
    int head = (e & 255) >> 6;
    float z = g_Z[i * Hh + head] + g_Z[(size_t)NN * Hh + i * Hh + head];
    out[e] = p / z;
}

// ---------------- launch ------------------------------------------------------
extern "C" void kernel_launch(void* const* d_in, const int* in_sizes, int n_in,
                              void* d_out, int out_size) {
    const float* x   = (const float*)d_in[0];
    const int*   adj = (const int*)  d_in[1];
    const float* W   = (const float*)d_in[2];
    const float* a1  = (const float*)d_in[3];
    const float* a2  = (const float*)d_in[4];
    float* out = (float*)d_out;

    cudaFuncSetAttribute(gat_agg, cudaFuncAttributeMaxDynamicSharedMemorySize, SMEM_BYTES);

    gemm_xw  <<<dim3(HD/64, NN/64), 256>>>(x, W);
    scores_k <<<(NN*Hh)/256, 256>>>(a1, a2);
    gat_agg  <<<dim3(NN/TI, JSPLIT), 256, SMEM_BYTES>>>(adj);
    epilogue_k<<<(NN*HD)/256, 256>>>(out);
}